// round 9
// baseline (speedup 1.0000x reference)
#include <cuda_runtime.h>
#include <cuda_fp16.h>
#include <math.h>
#include <stdint.h>

#define BB    64
#define INS   10000
#define EXPS  53
#define HID   1500
#define NC    2048
#define KX    1553
#define KXP   1664
#define S1    24
#define SPAN1 424           // 24*424 = 10176 >= 10000, mult of 8
#define S2    13
#define SPAN2 128           // 13*128 = 1664 exactly (2 chunks/block)

// stage: A fp16 64 rows x 144B (9216) @0 ; B fp32 64 rows x 528B (33792) @9216
#define OFF_B  9216
#define STG    43008
#define SMEM_T 86016        // 2 stages -> 2 CTAs/SM

#define CONVA_BLKS 2500     // 2500*256 = BB*INS exactly

// ---------------- device scratch ----------------
__device__ __align__(16) __half g_Ah[BB * INS];
__device__ float g_part1[S1][BB][HID];
__device__ __align__(16) __half g_xh[BB * KXP];
__device__ float g_part2[S2][BB][NC];
__device__ float g_cmax[32][NC];

__device__ __forceinline__ uint32_t smem_u32(const void* p) {
    uint32_t a;
    asm("{ .reg .u64 t; cvta.to.shared.u64 t, %1; cvt.u32.u64 %0, t; }" : "=r"(a) : "l"(p));
    return a;
}
#define LDX4(r, addr)                                                        \
    asm volatile("ldmatrix.sync.aligned.m8n8.x4.shared.b16 {%0,%1,%2,%3}, [%4];" \
        : "=r"((r)[0]), "=r"((r)[1]), "=r"((r)[2]), "=r"((r)[3]) : "r"(addr))
#define LDX4T(r, addr)                                                       \
    asm volatile("ldmatrix.sync.aligned.m8n8.x4.trans.shared.b16 {%0,%1,%2,%3}, [%4];" \
        : "=r"((r)[0]), "=r"((r)[1]), "=r"((r)[2]), "=r"((r)[3]) : "r"(addr))
#define MMA16816(d, a, b)                                                    \
    asm volatile("mma.sync.aligned.m16n8k16.row.col.f32.f16.f16.f32 "       \
        "{%0,%1,%2,%3}, {%4,%5,%6,%7}, {%8,%9}, {%0,%1,%2,%3};"              \
        : "+f"((d)[0]), "+f"((d)[1]), "+f"((d)[2]), "+f"((d)[3])             \
        : "r"((a)[0]), "r"((a)[1]), "r"((a)[2]), "r"((a)[3]),                \
          "r"((b)[0]), "r"((b)[1]))
__device__ __forceinline__ void cp16(uint32_t dst, const void* src, int src_bytes) {
    asm volatile("cp.async.cg.shared.global [%0], [%1], 16, %2;"
                 :: "r"(dst), "l"(src), "r"(src_bytes) : "memory");
}
#define CP_COMMIT()  asm volatile("cp.async.commit_group;" ::: "memory")
#define CP_WAIT(n)   asm volatile("cp.async.wait_group %0;" :: "n"(n) : "memory")

// ---------------------------------------------------------------------------
// HMMA fp16 split-K GEMM. A: preconverted fp16 [64][KA], cp.async direct.
// B: fp32 W [KB][Nn] via cp.async, converted in place to fp16 (conflict-free).
// part[split][m][n] = sum_{k in split} A[m,k] * W[k,n].
// Tile M=64 x N=128 x Kchunk=64; 256 thr; warp = 32(M) x 32(N); 2 CTAs/SM.
// B fp16 layout: row k, n-segment s (32 cols): fp16[32] @ k*528 + s*128.
// ---------------------------------------------------------------------------
__global__ __launch_bounds__(256, 2) void gemm_hmma(
    const __half* __restrict__ A, int KA,
    const float* __restrict__ W, int KB,
    float* __restrict__ part, int Nn, int span)
{
    extern __shared__ __align__(16) char sm[];
    const int tid = threadIdx.x, lane = tid & 31, w = tid >> 5;
    const int n0 = blockIdx.x * 128;
    const int k0 = blockIdx.y * span;
    const int kendA = min(k0 + span, KA);
    const int kendB = min(k0 + span, KB);
    const int nch = (kendA - k0 + 63) >> 6;
    const uint32_t sbase = smem_u32(sm);
    const int wm = (w & 1) * 32, wn = (w >> 1) * 32;

    float acc[2][4][4];
    #pragma unroll
    for (int i = 0; i < 2; i++)
        #pragma unroll
        for (int j = 0; j < 4; j++)
            #pragma unroll
            for (int e = 0; e < 4; e++) acc[i][j][e] = 0.f;

    const int aRow = lane & 15, aCol2 = (lane >> 4) * 16;   // bytes
    const int bRowT = lane & 15, bColT = (lane >> 4) * 8;
    const int bSeg = (w >> 1) * 128;

    // conflict-free convert mapping: row stride 528B = 132 words == 4 (mod 32)
    const int cvRow = (tid >> 5) * 8 + (tid & 7);   // 0..63
    const int cvSeg = (tid >> 3) & 3;               // 0..3 (128B fp32 -> 64B fp16)

    auto stage_cp = [&](int c) {
        const int kt = k0 + c * 64;
        const uint32_t sb = sbase + (uint32_t)(c & 1) * STG;
        #pragma unroll
        for (int u = 0; u < 2; u++) {          // A fp16: 512 granules
            int i = tid + u * 256;
            int m = i >> 3, g = i & 7;
            int gk = kt + g * 8;
            const __half* src = A + (size_t)m * KA + gk;
            int ok = (gk + 8 <= kendA) ? 16 : 0;
            cp16(sb + (uint32_t)(m * 144 + g * 16), src, ok);
        }
        #pragma unroll
        for (int u = 0; u < 8; u++) {          // B fp32: 2048 granules
            int j = tid + u * 256;
            int r = j >> 5, g = j & 31;
            int gk = kt + r, n = n0 + g * 4;
            const float* src = W + (size_t)gk * Nn + n;
            int ok = (gk < kendB && n + 4 <= Nn) ? 16 : 0;
            cp16(sb + OFF_B + (uint32_t)(r * 528 + g * 16), src, ok);
        }
        CP_COMMIT();
    };

    stage_cp(0);

    for (int c = 0; c < nch; c++) {
        if (c + 1 < nch) { stage_cp(c + 1); CP_WAIT(1); }
        else             { CP_WAIT(0); }
        __syncthreads();

        // ---- in-place convert B fp32 -> fp16, conflict-free lanes
        {
            char* pr = sm + (c & 1) * STG + OFF_B + cvRow * 528 + cvSeg * 128;
            float4 v[8];
            #pragma unroll
            for (int i = 0; i < 8; i++) v[i] = *(const float4*)(pr + i * 16);
            uint4 o[4];
            #pragma unroll
            for (int i = 0; i < 4; i++) {
                __half2 h0 = __floats2half2_rn(v[2*i].x,   v[2*i].y);
                __half2 h1 = __floats2half2_rn(v[2*i].z,   v[2*i].w);
                __half2 h2 = __floats2half2_rn(v[2*i+1].x, v[2*i+1].y);
                __half2 h3 = __floats2half2_rn(v[2*i+1].z, v[2*i+1].w);
                o[i] = make_uint4(*(uint32_t*)&h0, *(uint32_t*)&h1,
                                  *(uint32_t*)&h2, *(uint32_t*)&h3);
            }
            #pragma unroll
            for (int i = 0; i < 4; i++)
                *(uint4*)(pr + i * 16) = o[i];   // 64B fp16 into own region head
        }
        __syncthreads();

        const uint32_t sb = sbase + (uint32_t)(c & 1) * STG;
        #pragma unroll
        for (int ks = 0; ks < 4; ks++) {
            uint32_t af[2][4], bf[2][4];
            #pragma unroll
            for (int mi = 0; mi < 2; mi++)
                LDX4(af[mi], sb + (wm + mi * 16 + aRow) * 144 + ks * 32 + aCol2);
            #pragma unroll
            for (int p = 0; p < 2; p++)
                LDX4T(bf[p], sb + OFF_B + (ks * 16 + bRowT) * 528 + bSeg
                             + (p * 16 + bColT) * 2);
            #pragma unroll
            for (int mi = 0; mi < 2; mi++)
                #pragma unroll
                for (int ni = 0; ni < 4; ni++)
                    MMA16816(acc[mi][ni], af[mi], (&bf[ni >> 1][(ni & 1) * 2]));
        }
        __syncthreads();
    }

    float* pb = part + (size_t)blockIdx.y * 64 * Nn;
    #pragma unroll
    for (int mi = 0; mi < 2; mi++)
        #pragma unroll
        for (int ni = 0; ni < 4; ni++) {
            int r0 = wm + mi * 16 + (lane >> 2);
            int cc = n0 + wn + ni * 8 + (lane & 3) * 2;
            if (cc < Nn) {
                pb[r0 * Nn + cc] = acc[mi][ni][0];
                pb[(r0 + 8) * Nn + cc] = acc[mi][ni][2];
            }
            if (cc + 1 < Nn) {
                pb[r0 * Nn + cc + 1] = acc[mi][ni][1];
                pb[(r0 + 8) * Nn + cc + 1] = acc[mi][ni][3];
            }
        }
}

// ---------------- prep: convA(fp16) + hpo column-max strips ----------------
__global__ void prep(const float* __restrict__ A, const float* __restrict__ hpo)
{
    int bx = blockIdx.x;
    if (bx < CONVA_BLKS) {
        int idx = bx * 256 + threadIdx.x;
        g_Ah[idx] = __float2half(A[idx]);
    } else {
        int cb = bx - CONVA_BLKS;                  // 0..255
        int strip = cb >> 3;
        int j = (cb & 7) * 256 + threadIdx.x;
        const float* col = hpo + (size_t)(strip * 64) * NC + j;
        float m = col[0];
        #pragma unroll 8
        for (int i = 1; i < 64; i++)
            m = fmaxf(m, col[(size_t)i * NC]);
        g_cmax[strip][j] = m;
    }
}

// ---------------- fuse1: partials + bias + GELU + concat -> fp16 -----------
__global__ void fuse1(const float* __restrict__ b1, const float* __restrict__ expx)
{
    int idx = blockIdx.x * 256 + threadIdx.x;
    if (idx >= BB * KXP) return;
    int b = idx / KXP, n = idx - b * KXP;
    float v;
    if (n < HID) {
        float s = b1[n];
        #pragma unroll
        for (int p = 0; p < S1; p++) s += g_part1[p][b][n];
        v = 0.5f * s * (1.f + erff(s * 0.70710678118654752f));
    } else if (n < KX) {
        v = expx[b * EXPS + (n - HID)];
    } else {
        v = 0.f;
    }
    g_xh[idx] = __float2half(v);
}

// out[b,j] = sigmoid(sum + b2[j]) * max_i hpo[i,j]  (exact factorization)
__global__ void final_k(const float* __restrict__ b2, float* __restrict__ out)
{
    int j = blockIdx.x * 256 + threadIdx.x;
    int b = blockIdx.y;
    float m = g_cmax[0][j];
    #pragma unroll
    for (int p = 1; p < 32; p++) m = fmaxf(m, g_cmax[p][j]);
    float s = b2[j];
    #pragma unroll
    for (int p = 0; p < S2; p++) s += g_part2[p][b][j];
    out[b * NC + j] = m / (1.f + expf(-s));
}

// ---------------- launcher ----------------
extern "C" void kernel_launch(void* const* d_in, const int* in_sizes, int n_in,
                              void* d_out, int out_size)
{
    const float* gos  = (const float*)d_in[0];
    const float* expx = (const float*)d_in[1];
    const float* W1   = (const float*)d_in[2];
    const float* b1   = (const float*)d_in[3];
    const float* W2   = (const float*)d_in[4];
    const float* b2   = (const float*)d_in[5];
    const float* hpo  = (const float*)d_in[6];
    float* out = (float*)d_out;

    cudaFuncSetAttribute(gemm_hmma, cudaFuncAttributeMaxDynamicSharedMemorySize, SMEM_T);

    __half *ah, *xh;
    float *p1, *p2;
    cudaGetSymbolAddress((void**)&ah, g_Ah);
    cudaGetSymbolAddress((void**)&xh, g_xh);
    cudaGetSymbolAddress((void**)&p1, g_part1);
    cudaGetSymbolAddress((void**)&p2, g_part2);

    prep<<<CONVA_BLKS + 256, 256>>>(gos, hpo);

    // GEMM1: (64 x 10000) @ W1(10000 x 1500), split-K 24 -> 288 blocks (2/SM)
    gemm_hmma<<<dim3(12, S1), 256, SMEM_T>>>(ah, INS, W1, INS, p1, HID, SPAN1);

    fuse1<<<(BB * KXP) / 256, 256>>>(b1, expx);

    // GEMM2: (64 x 1664pad) @ W2(1553 x 2048), split-K 13 -> 208 blocks, 2 chunks
    gemm_hmma<<<dim3(16, S2), 256, SMEM_T>>>(xh, KXP, W2, KX, p2, NC, SPAN2);

    final_k<<<dim3(NC / 256, BB), 256>>>(b2, out);
}

// round 10
// speedup vs baseline: 1.1671x; 1.1671x over previous
#include <cuda_runtime.h>
#include <cuda_fp16.h>
#include <math.h>
#include <stdint.h>

#define BB    64
#define INS   10000
#define EXPS  53
#define HID   1500
#define NC    2048
#define KX    1553
#define KXP   1664
#define S1    18
#define SPAN1 568           // 18*568 = 10224 >= 10000, mult of 8
#define S2    9
#define SPAN2 192           // 9*192 = 1728 >= 1664, mult of 8

// ---------------- device scratch ----------------
__device__ float g_part1[S1][BB][HID];
__device__ __align__(16) __half g_xh[BB * KXP];
__device__ float g_part2[S2][BB][NC];
__device__ float g_cmax[32][NC];

__device__ __forceinline__ uint32_t smem_u32(const void* p) {
    uint32_t a;
    asm("{ .reg .u64 t; cvta.to.shared.u64 t, %1; cvt.u32.u64 %0, t; }" : "=r"(a) : "l"(p));
    return a;
}
#define LDX4(r, addr)                                                        \
    asm volatile("ldmatrix.sync.aligned.m8n8.x4.shared.b16 {%0,%1,%2,%3}, [%4];" \
        : "=r"((r)[0]), "=r"((r)[1]), "=r"((r)[2]), "=r"((r)[3]) : "r"(addr))
#define LDX4T(r, addr)                                                       \
    asm volatile("ldmatrix.sync.aligned.m8n8.x4.trans.shared.b16 {%0,%1,%2,%3}, [%4];" \
        : "=r"((r)[0]), "=r"((r)[1]), "=r"((r)[2]), "=r"((r)[3]) : "r"(addr))
#define MMA16816(d, a, b)                                                    \
    asm volatile("mma.sync.aligned.m16n8k16.row.col.f32.f16.f16.f32 "       \
        "{%0,%1,%2,%3}, {%4,%5,%6,%7}, {%8,%9}, {%0,%1,%2,%3};"              \
        : "+f"((d)[0]), "+f"((d)[1]), "+f"((d)[2]), "+f"((d)[3])             \
        : "r"((a)[0]), "r"((a)[1]), "r"((a)[2]), "r"((a)[3]),                \
          "r"((b)[0]), "r"((b)[1]))
__device__ __forceinline__ void cp16(uint32_t dst, const void* src, int src_bytes) {
    asm volatile("cp.async.cg.shared.global [%0], [%1], 16, %2;"
                 :: "r"(dst), "l"(src), "r"(src_bytes) : "memory");
}
#define CP_COMMIT()  asm volatile("cp.async.commit_group;" ::: "memory")
#define CP_WAIT(n)   asm volatile("cp.async.wait_group %0;" :: "n"(n) : "memory")

// ---------------------------------------------------------------------------
// HMMA fp16 split-K GEMM, templated on A dtype.
//   AF32=1: A fp32 [64][KA] -> converted fp16 in place (GEMM1, A=gos raw).
//   AF32=0: A fp16 [64][KA] (GEMM2, A=g_xh from fuse1).
// B: fp32 W [KB][Nn] via cp.async, in-place fp16 convert per chunk.
// part[split][m][n] = sum_{k in split} A[m,k] * W[k,n].
// Tile M=64 x N=128 x Kchunk=64; 256 thr; warp = 32(M) x 32(N); 2 CTAs/SM.
// A fp16 layout (AF32): row m, k-seg s (16 k): fp16[16] @ m*272 + s*64.
// A fp16 layout (!AF32): row m: fp16[span 8-granules] @ m*144 + g*16.
// B fp16 layout: row k, n-seg s (32 n): fp16[32] @ k*528 + s*128.
// Blocks with flat id >= ngemm do hpo column-max strips instead (GEMM1 only).
// ---------------------------------------------------------------------------
template<bool AF32>
__global__ __launch_bounds__(256, 2) void gemm_tpl(
    const void* __restrict__ Av, int KA,
    const float* __restrict__ W, int KB,
    float* __restrict__ part, int Nn, int span,
    int nbx, int ngemm, const float* __restrict__ hpo)
{
    const int tid = threadIdx.x;
    const int bid = blockIdx.x;
    if (bid >= ngemm) {                        // fused hpo colmax strips
        int cb = bid - ngemm;                  // 0..255
        int strip = cb >> 3;
        int j = (cb & 7) * 256 + tid;
        const float* col = hpo + (size_t)(strip * 64) * NC + j;
        float m = col[0];
        #pragma unroll 8
        for (int i = 1; i < 64; i++)
            m = fmaxf(m, col[(size_t)i * NC]);
        g_cmax[strip][j] = m;
        return;
    }

    constexpr int ASTR  = AF32 ? 272 : 144;    // A row stride bytes
    constexpr int OFF_B = AF32 ? 17408 : 9216;
    constexpr int STG   = OFF_B + 33792;

    extern __shared__ __align__(16) char sm[];
    const int lane = tid & 31, w = tid >> 5;
    const int n0 = (bid % nbx) * 128;
    const int k0 = (bid / nbx) * span;
    const int kendA = min(k0 + span, KA);
    const int kendB = min(k0 + span, KB);
    const int nch = (kendA - k0 + 63) >> 6;
    const uint32_t sbase = smem_u32(sm);
    const int wm = (w & 1) * 32, wn = (w >> 1) * 32;

    float acc[2][4][4];
    #pragma unroll
    for (int i = 0; i < 2; i++)
        #pragma unroll
        for (int j = 0; j < 4; j++)
            #pragma unroll
            for (int e = 0; e < 4; e++) acc[i][j][e] = 0.f;

    const int aRow = lane & 15, aCol2 = (lane >> 4) * 16;   // bytes
    const int bRowT = lane & 15, bColT = (lane >> 4) * 8;
    const int bSeg = (w >> 1) * 128;

    // B convert mapping (row stride 528B = 132 words == 4 mod 32)
    const int cvRow = (tid >> 5) * 8 + (tid & 7);
    const int cvSeg = (tid >> 3) & 3;

    auto stage_cp = [&](int c) {
        const int kt = k0 + c * 64;
        const uint32_t sb = sbase + (uint32_t)(c & 1) * STG;
        if (AF32) {
            #pragma unroll
            for (int u = 0; u < 4; u++) {      // A fp32: 1024 granules of 4 floats
                int i = tid + u * 256;
                int m = i >> 4, g = i & 15;
                int gk = kt + g * 4;
                const float* src = (const float*)Av + (size_t)m * KA + gk;
                int ok = (gk + 4 <= kendA) ? 16 : 0;
                cp16(sb + (uint32_t)(m * 272 + g * 16), src, ok);
            }
        } else {
            #pragma unroll
            for (int u = 0; u < 2; u++) {      // A fp16: 512 granules of 8 halves
                int i = tid + u * 256;
                int m = i >> 3, g = i & 7;
                int gk = kt + g * 8;
                const __half* src = (const __half*)Av + (size_t)m * KA + gk;
                int ok = (gk + 8 <= kendA) ? 16 : 0;
                cp16(sb + (uint32_t)(m * 144 + g * 16), src, ok);
            }
        }
        #pragma unroll
        for (int u = 0; u < 8; u++) {          // B fp32: 2048 granules
            int j = tid + u * 256;
            int r = j >> 5, g = j & 31;
            int gk = kt + r, n = n0 + g * 4;
            const float* src = W + (size_t)gk * Nn + n;
            int ok = (gk < kendB && n + 4 <= Nn) ? 16 : 0;
            cp16(sb + OFF_B + (uint32_t)(r * 528 + g * 16), src, ok);
        }
        CP_COMMIT();
    };

    stage_cp(0);

    for (int c = 0; c < nch; c++) {
        if (c + 1 < nch) { stage_cp(c + 1); CP_WAIT(1); }
        else             { CP_WAIT(0); }
        __syncthreads();

        {   // ---- in-place converts (each thread: write subset of own read region)
            char* stg = sm + (c & 1) * STG;
            if (AF32) {
                // A: row r = tid&63, k-seg s = tid>>6 (16 floats @ r*272+s*64)
                char* pa = stg + (tid & 63) * 272 + (tid >> 6) * 64;
                float4 va[4];
                #pragma unroll
                for (int i = 0; i < 4; i++) va[i] = *(const float4*)(pa + i * 16);
                uint4 oa[2];
                #pragma unroll
                for (int i = 0; i < 2; i++) {
                    __half2 h0 = __floats2half2_rn(va[2*i].x,   va[2*i].y);
                    __half2 h1 = __floats2half2_rn(va[2*i].z,   va[2*i].w);
                    __half2 h2 = __floats2half2_rn(va[2*i+1].x, va[2*i+1].y);
                    __half2 h3 = __floats2half2_rn(va[2*i+1].z, va[2*i+1].w);
                    oa[i] = make_uint4(*(uint32_t*)&h0, *(uint32_t*)&h1,
                                       *(uint32_t*)&h2, *(uint32_t*)&h3);
                }
                *(uint4*)(pa)      = oa[0];
                *(uint4*)(pa + 16) = oa[1];
            }
            // B: 32 floats per thread
            char* pr = stg + OFF_B + cvRow * 528 + cvSeg * 128;
            float4 v[8];
            #pragma unroll
            for (int i = 0; i < 8; i++) v[i] = *(const float4*)(pr + i * 16);
            uint4 o[4];
            #pragma unroll
            for (int i = 0; i < 4; i++) {
                __half2 h0 = __floats2half2_rn(v[2*i].x,   v[2*i].y);
                __half2 h1 = __floats2half2_rn(v[2*i].z,   v[2*i].w);
                __half2 h2 = __floats2half2_rn(v[2*i+1].x, v[2*i+1].y);
                __half2 h3 = __floats2half2_rn(v[2*i+1].z, v[2*i+1].w);
                o[i] = make_uint4(*(uint32_t*)&h0, *(uint32_t*)&h1,
                                  *(uint32_t*)&h2, *(uint32_t*)&h3);
            }
            #pragma unroll
            for (int i = 0; i < 4; i++)
                *(uint4*)(pr + i * 16) = o[i];
        }
        __syncthreads();

        const uint32_t sb = sbase + (uint32_t)(c & 1) * STG;
        #pragma unroll
        for (int ks = 0; ks < 4; ks++) {
            uint32_t af[2][4], bf[2][4];
            #pragma unroll
            for (int mi = 0; mi < 2; mi++) {
                uint32_t ad = AF32
                    ? sb + (wm + mi * 16 + aRow) * 272 + ks * 64 + aCol2
                    : sb + (wm + mi * 16 + aRow) * 144 + ks * 32 + aCol2;
                LDX4(af[mi], ad);
            }
            #pragma unroll
            for (int p = 0; p < 2; p++)
                LDX4T(bf[p], sb + OFF_B + (ks * 16 + bRowT) * 528 + bSeg
                             + (p * 16 + bColT) * 2);
            #pragma unroll
            for (int mi = 0; mi < 2; mi++)
                #pragma unroll
                for (int ni = 0; ni < 4; ni++)
                    MMA16816(acc[mi][ni], af[mi], (&bf[ni >> 1][(ni & 1) * 2]));
        }
        __syncthreads();
    }

    float* pb = part + (size_t)(bid / nbx) * 64 * Nn;
    #pragma unroll
    for (int mi = 0; mi < 2; mi++)
        #pragma unroll
        for (int ni = 0; ni < 4; ni++) {
            int r0 = wm + mi * 16 + (lane >> 2);
            int cc = n0 + wn + ni * 8 + (lane & 3) * 2;
            if (cc < Nn) {
                pb[r0 * Nn + cc] = acc[mi][ni][0];
                pb[(r0 + 8) * Nn + cc] = acc[mi][ni][2];
            }
            if (cc + 1 < Nn) {
                pb[r0 * Nn + cc + 1] = acc[mi][ni][1];
                pb[(r0 + 8) * Nn + cc + 1] = acc[mi][ni][3];
            }
        }
}

// ---------------- fuse1: partials + bias + GELU + concat -> fp16 -----------
__global__ void fuse1(const float* __restrict__ b1, const float* __restrict__ expx)
{
    int idx = blockIdx.x * 256 + threadIdx.x;
    if (idx >= BB * KXP) return;
    int b = idx / KXP, n = idx - b * KXP;
    float v;
    if (n < HID) {
        float s = b1[n];
        #pragma unroll
        for (int p = 0; p < S1; p++) s += g_part1[p][b][n];
        v = 0.5f * s * (1.f + erff(s * 0.70710678118654752f));
    } else if (n < KX) {
        v = expx[b * EXPS + (n - HID)];
    } else {
        v = 0.f;
    }
    g_xh[idx] = __float2half(v);
}

// out[b,j] = sigmoid(sum + b2[j]) * max_i hpo[i,j]  (exact factorization)
__global__ void final_k(const float* __restrict__ b2, float* __restrict__ out)
{
    int j = blockIdx.x * 256 + threadIdx.x;
    int b = blockIdx.y;
    float m = g_cmax[0][j];
    #pragma unroll
    for (int p = 1; p < 32; p++) m = fmaxf(m, g_cmax[p][j]);
    float s = b2[j];
    #pragma unroll
    for (int p = 0; p < S2; p++) s += g_part2[p][b][j];
    out[b * NC + j] = m / (1.f + expf(-s));
}

// ---------------- launcher ----------------
extern "C" void kernel_launch(void* const* d_in, const int* in_sizes, int n_in,
                              void* d_out, int out_size)
{
    const float* gos  = (const float*)d_in[0];
    const float* expx = (const float*)d_in[1];
    const float* W1   = (const float*)d_in[2];
    const float* b1   = (const float*)d_in[3];
    const float* W2   = (const float*)d_in[4];
    const float* b2   = (const float*)d_in[5];
    const float* hpo  = (const float*)d_in[6];
    float* out = (float*)d_out;

    cudaFuncSetAttribute(gemm_tpl<true>,  cudaFuncAttributeMaxDynamicSharedMemorySize,
                         2 * (17408 + 33792));
    cudaFuncSetAttribute(gemm_tpl<false>, cudaFuncAttributeMaxDynamicSharedMemorySize,
                         2 * (9216 + 33792));

    __half* xh;
    float *p1, *p2;
    cudaGetSymbolAddress((void**)&xh, g_xh);
    cudaGetSymbolAddress((void**)&p1, g_part1);
    cudaGetSymbolAddress((void**)&p2, g_part2);

    // GEMM1 (A = raw fp32 gos) + fused hpo colmax: 12*18 gemm blocks + 256 strips
    gemm_tpl<true><<<12 * S1 + 256, 256, 2 * (17408 + 33792)>>>(
        gos, INS, W1, INS, p1, HID, SPAN1, 12, 12 * S1, hpo);

    fuse1<<<(BB * KXP) / 256, 256>>>(b1, expx);

    // GEMM2 (A = fp16 g_xh): 16*9 = 144 blocks, 3 chunks each
    gemm_tpl<false><<<16 * S2, 256, 2 * (9216 + 33792)>>>(
        xh, KXP, W2, KX, p2, NC, SPAN2, 16, 16 * S2, hpo);

    final_k<<<dim3(NC / 256, BB), 256>>>(b2, out);
}

// round 11
// speedup vs baseline: 1.1913x; 1.0208x over previous
#include <cuda_runtime.h>
#include <cuda_fp16.h>
#include <math.h>
#include <stdint.h>

#define BB    64
#define INS   10000
#define EXPS  53
#define HID   1500
#define NC    2048
#define KX    1553
#define KXP   1664
#define S1    18
#define SPAN1 568           // 18*568 = 10224 >= 10000, mult of 8
#define S2    9
#define SPAN2 192           // 9*192 = 1728 >= 1664, mult of 8

#define FUSE1_BLKS ((BB * KXP) / 256)   // 416

// ---------------- device scratch ----------------
__device__ float g_part1[S1][BB][HID];
__device__ __align__(16) __half g_xh[BB * KXP];
__device__ float g_part2[S2][BB][NC];
__device__ float g_cmax[32][NC];
__device__ float g_cmaxF[NC];

__device__ __forceinline__ uint32_t smem_u32(const void* p) {
    uint32_t a;
    asm("{ .reg .u64 t; cvta.to.shared.u64 t, %1; cvt.u32.u64 %0, t; }" : "=r"(a) : "l"(p));
    return a;
}
#define LDX4(r, addr)                                                        \
    asm volatile("ldmatrix.sync.aligned.m8n8.x4.shared.b16 {%0,%1,%2,%3}, [%4];" \
        : "=r"((r)[0]), "=r"((r)[1]), "=r"((r)[2]), "=r"((r)[3]) : "r"(addr))
#define LDX4T(r, addr)                                                       \
    asm volatile("ldmatrix.sync.aligned.m8n8.x4.trans.shared.b16 {%0,%1,%2,%3}, [%4];" \
        : "=r"((r)[0]), "=r"((r)[1]), "=r"((r)[2]), "=r"((r)[3]) : "r"(addr))
#define MMA16816(d, a, b)                                                    \
    asm volatile("mma.sync.aligned.m16n8k16.row.col.f32.f16.f16.f32 "       \
        "{%0,%1,%2,%3}, {%4,%5,%6,%7}, {%8,%9}, {%0,%1,%2,%3};"              \
        : "+f"((d)[0]), "+f"((d)[1]), "+f"((d)[2]), "+f"((d)[3])             \
        : "r"((a)[0]), "r"((a)[1]), "r"((a)[2]), "r"((a)[3]),                \
          "r"((b)[0]), "r"((b)[1]))
__device__ __forceinline__ void cp16(uint32_t dst, const void* src, int src_bytes) {
    asm volatile("cp.async.cg.shared.global [%0], [%1], 16, %2;"
                 :: "r"(dst), "l"(src), "r"(src_bytes) : "memory");
}
#define CP_COMMIT()  asm volatile("cp.async.commit_group;" ::: "memory")
#define CP_WAIT(n)   asm volatile("cp.async.wait_group %0;" :: "n"(n) : "memory")

// ---------------------------------------------------------------------------
// HMMA fp16 split-K GEMM, templated on A dtype (see R10 notes).
// Blocks with flat id >= ngemm do hpo column-max strips (GEMM1 launch only).
// ---------------------------------------------------------------------------
template<bool AF32>
__global__ __launch_bounds__(256, 2) void gemm_tpl(
    const void* __restrict__ Av, int KA,
    const float* __restrict__ W, int KB,
    float* __restrict__ part, int Nn, int span,
    int nbx, int ngemm, const float* __restrict__ hpo)
{
    const int tid = threadIdx.x;
    const int bid = blockIdx.x;
    if (bid >= ngemm) {                        // fused hpo colmax strips
        int cb = bid - ngemm;                  // 0..255
        int strip = cb >> 3;
        int j = (cb & 7) * 256 + tid;
        const float* col = hpo + (size_t)(strip * 64) * NC + j;
        float m = col[0];
        #pragma unroll 8
        for (int i = 1; i < 64; i++)
            m = fmaxf(m, col[(size_t)i * NC]);
        g_cmax[strip][j] = m;
        return;
    }

    constexpr int OFF_B = AF32 ? 17408 : 9216;
    constexpr int STG   = OFF_B + 33792;

    extern __shared__ __align__(16) char sm[];
    const int lane = tid & 31, w = tid >> 5;
    const int n0 = (bid % nbx) * 128;
    const int k0 = (bid / nbx) * span;
    const int kendA = min(k0 + span, KA);
    const int kendB = min(k0 + span, KB);
    const int nch = (kendA - k0 + 63) >> 6;
    const uint32_t sbase = smem_u32(sm);
    const int wm = (w & 1) * 32, wn = (w >> 1) * 32;

    float acc[2][4][4];
    #pragma unroll
    for (int i = 0; i < 2; i++)
        #pragma unroll
        for (int j = 0; j < 4; j++)
            #pragma unroll
            for (int e = 0; e < 4; e++) acc[i][j][e] = 0.f;

    const int aRow = lane & 15, aCol2 = (lane >> 4) * 16;   // bytes
    const int bRowT = lane & 15, bColT = (lane >> 4) * 8;
    const int bSeg = (w >> 1) * 128;
    const int cvRow = (tid >> 5) * 8 + (tid & 7);
    const int cvSeg = (tid >> 3) & 3;

    auto stage_cp = [&](int c) {
        const int kt = k0 + c * 64;
        const uint32_t sb = sbase + (uint32_t)(c & 1) * STG;
        if (AF32) {
            #pragma unroll
            for (int u = 0; u < 4; u++) {      // A fp32: 1024 granules
                int i = tid + u * 256;
                int m = i >> 4, g = i & 15;
                int gk = kt + g * 4;
                const float* src = (const float*)Av + (size_t)m * KA + gk;
                int ok = (gk + 4 <= kendA) ? 16 : 0;
                cp16(sb + (uint32_t)(m * 272 + g * 16), src, ok);
            }
        } else {
            #pragma unroll
            for (int u = 0; u < 2; u++) {      // A fp16: 512 granules
                int i = tid + u * 256;
                int m = i >> 3, g = i & 7;
                int gk = kt + g * 8;
                const __half* src = (const __half*)Av + (size_t)m * KA + gk;
                int ok = (gk + 8 <= kendA) ? 16 : 0;
                cp16(sb + (uint32_t)(m * 144 + g * 16), src, ok);
            }
        }
        #pragma unroll
        for (int u = 0; u < 8; u++) {          // B fp32: 2048 granules
            int j = tid + u * 256;
            int r = j >> 5, g = j & 31;
            int gk = kt + r, n = n0 + g * 4;
            const float* src = W + (size_t)gk * Nn + n;
            int ok = (gk < kendB && n + 4 <= Nn) ? 16 : 0;
            cp16(sb + OFF_B + (uint32_t)(r * 528 + g * 16), src, ok);
        }
        CP_COMMIT();
    };

    stage_cp(0);

    for (int c = 0; c < nch; c++) {
        if (c + 1 < nch) { stage_cp(c + 1); CP_WAIT(1); }
        else             { CP_WAIT(0); }
        __syncthreads();

        {   // ---- in-place converts
            char* stg = sm + (c & 1) * STG;
            if (AF32) {
                char* pa = stg + (tid & 63) * 272 + (tid >> 6) * 64;
                float4 va[4];
                #pragma unroll
                for (int i = 0; i < 4; i++) va[i] = *(const float4*)(pa + i * 16);
                uint4 oa[2];
                #pragma unroll
                for (int i = 0; i < 2; i++) {
                    __half2 h0 = __floats2half2_rn(va[2*i].x,   va[2*i].y);
                    __half2 h1 = __floats2half2_rn(va[2*i].z,   va[2*i].w);
                    __half2 h2 = __floats2half2_rn(va[2*i+1].x, va[2*i+1].y);
                    __half2 h3 = __floats2half2_rn(va[2*i+1].z, va[2*i+1].w);
                    oa[i] = make_uint4(*(uint32_t*)&h0, *(uint32_t*)&h1,
                                       *(uint32_t*)&h2, *(uint32_t*)&h3);
                }
                *(uint4*)(pa)      = oa[0];
                *(uint4*)(pa + 16) = oa[1];
            }
            char* pr = stg + OFF_B + cvRow * 528 + cvSeg * 128;
            float4 v[8];
            #pragma unroll
            for (int i = 0; i < 8; i++) v[i] = *(const float4*)(pr + i * 16);
            uint4 o[4];
            #pragma unroll
            for (int i = 0; i < 4; i++) {
                __half2 h0 = __floats2half2_rn(v[2*i].x,   v[2*i].y);
                __half2 h1 = __floats2half2_rn(v[2*i].z,   v[2*i].w);
                __half2 h2 = __floats2half2_rn(v[2*i+1].x, v[2*i+1].y);
                __half2 h3 = __floats2half2_rn(v[2*i+1].z, v[2*i+1].w);
                o[i] = make_uint4(*(uint32_t*)&h0, *(uint32_t*)&h1,
                                  *(uint32_t*)&h2, *(uint32_t*)&h3);
            }
            #pragma unroll
            for (int i = 0; i < 4; i++)
                *(uint4*)(pr + i * 16) = o[i];
        }
        __syncthreads();

        const uint32_t sb = sbase + (uint32_t)(c & 1) * STG;
        #pragma unroll
        for (int ks = 0; ks < 4; ks++) {
            uint32_t af[2][4], bf[2][4];
            #pragma unroll
            for (int mi = 0; mi < 2; mi++) {
                uint32_t ad = AF32
                    ? sb + (wm + mi * 16 + aRow) * 272 + ks * 64 + aCol2
                    : sb + (wm + mi * 16 + aRow) * 144 + ks * 32 + aCol2;
                LDX4(af[mi], ad);
            }
            #pragma unroll
            for (int p = 0; p < 2; p++)
                LDX4T(bf[p], sb + OFF_B + (ks * 16 + bRowT) * 528 + bSeg
                             + (p * 16 + bColT) * 2);
            #pragma unroll
            for (int mi = 0; mi < 2; mi++)
                #pragma unroll
                for (int ni = 0; ni < 4; ni++)
                    MMA16816(acc[mi][ni], af[mi], (&bf[ni >> 1][(ni & 1) * 2]));
        }
        __syncthreads();
    }

    float* pb = part + (size_t)(bid / nbx) * 64 * Nn;
    #pragma unroll
    for (int mi = 0; mi < 2; mi++)
        #pragma unroll
        for (int ni = 0; ni < 4; ni++) {
            int r0 = wm + mi * 16 + (lane >> 2);
            int cc = n0 + wn + ni * 8 + (lane & 3) * 2;
            if (cc < Nn) {
                pb[r0 * Nn + cc] = acc[mi][ni][0];
                pb[(r0 + 8) * Nn + cc] = acc[mi][ni][2];
            }
            if (cc + 1 < Nn) {
                pb[r0 * Nn + cc + 1] = acc[mi][ni][1];
                pb[(r0 + 8) * Nn + cc + 1] = acc[mi][ni][3];
            }
        }
}

// ---- fuse1: partials + bias + GELU + concat -> fp16 ; tail blocks: cmax 32->1
__global__ void fuse1(const float* __restrict__ b1, const float* __restrict__ expx)
{
    int bx = blockIdx.x;
    if (bx >= FUSE1_BLKS) {                    // 8 tail blocks: collapse strips
        int j = (bx - FUSE1_BLKS) * 256 + threadIdx.x;   // 0..2047
        float m = g_cmax[0][j];
        #pragma unroll
        for (int p = 1; p < 32; p++) m = fmaxf(m, g_cmax[p][j]);
        g_cmaxF[j] = m;
        return;
    }
    int idx = bx * 256 + threadIdx.x;
    int b = idx / KXP, n = idx - b * KXP;
    float v;
    if (n < HID) {
        float s = b1[n];
        #pragma unroll
        for (int p = 0; p < S1; p++) s += g_part1[p][b][n];
        v = 0.5f * s * (1.f + erff(s * 0.70710678118654752f));
    } else if (n < KX) {
        v = expx[b * EXPS + (n - HID)];
    } else {
        v = 0.f;
    }
    g_xh[idx] = __float2half(v);
}

// out[b,j] = sigmoid(sum + b2[j]) * cmaxF[j]  (exact factorization)
__global__ void final_k(const float* __restrict__ b2, float* __restrict__ out)
{
    int j = blockIdx.x * 256 + threadIdx.x;
    int b = blockIdx.y;
    float m = g_cmaxF[j];
    float s = b2[j];
    #pragma unroll
    for (int p = 0; p < S2; p++) s += g_part2[p][b][j];
    out[b * NC + j] = m / (1.f + expf(-s));
}

// ---------------- launcher ----------------
extern "C" void kernel_launch(void* const* d_in, const int* in_sizes, int n_in,
                              void* d_out, int out_size)
{
    const float* gos  = (const float*)d_in[0];
    const float* expx = (const float*)d_in[1];
    const float* W1   = (const float*)d_in[2];
    const float* b1   = (const float*)d_in[3];
    const float* W2   = (const float*)d_in[4];
    const float* b2   = (const float*)d_in[5];
    const float* hpo  = (const float*)d_in[6];
    float* out = (float*)d_out;

    cudaFuncSetAttribute(gemm_tpl<true>,  cudaFuncAttributeMaxDynamicSharedMemorySize,
                         2 * (17408 + 33792));
    cudaFuncSetAttribute(gemm_tpl<false>, cudaFuncAttributeMaxDynamicSharedMemorySize,
                         2 * (9216 + 33792));

    __half* xh;
    float *p1, *p2;
    cudaGetSymbolAddress((void**)&xh, g_xh);
    cudaGetSymbolAddress((void**)&p1, g_part1);
    cudaGetSymbolAddress((void**)&p2, g_part2);

    // GEMM1 (A = raw fp32 gos) + fused hpo colmax strips
    gemm_tpl<true><<<12 * S1 + 256, 256, 2 * (17408 + 33792)>>>(
        gos, INS, W1, INS, p1, HID, SPAN1, 12, 12 * S1, hpo);

    // fuse1 + cmax strip collapse (8 tail blocks)
    fuse1<<<FUSE1_BLKS + 8, 256>>>(b1, expx);

    // GEMM2 (A = fp16 g_xh): 144 blocks, 3 chunks each
    gemm_tpl<false><<<16 * S2, 256, 2 * (9216 + 33792)>>>(
        xh, KXP, W2, KX, p2, NC, SPAN2, 16, 16 * S2, hpo);

    final_k<<<dim3(NC / 256, BB), 256>>>(b2, out);
}